// round 7
// baseline (speedup 1.0000x reference)
#include <cuda_runtime.h>
#include <cstdint>

// Conv2d direct: input (64,8,256,256) f32 NCHW, filter (8,8,3,3) OIHW,
// VALID, stride 1 -> out (64,8,254,254) f32.
//
// R6: occupancy push. Same f32x2 column-pair scheme as R5, but JPT=3 so
// per-thread state fits ~62 regs -> __launch_bounds__(256,4): 4 CTAs/SM,
// 32 warps, occ ~50% to hide LDS latency (issue% was the limiter at 53%).

#define CONV_N 64
#define CONV_C 8
#define CONV_H 256
#define CONV_W 256
#define CONV_M 8
#define CONV_P 254
#define CONV_Q 254

#define TILE_W 64      // 32 threads x 2 cols
#define TILE_H 12      // 4 row-groups x 3 rows
#define JPT 3          // rows per thread
#define MH  4          // m channels per thread (half of 8)

#define ROWS_S (TILE_H + 2)   // 14
#define COLS_S 66

typedef unsigned long long ull;

__global__ __launch_bounds__(256, 4)
void Im2Col_Conv2d_6854767804820_kernel(const float* __restrict__ in,
                                        const float* __restrict__ filt,
                                        float* __restrict__ out)
{
    __shared__ float sIn[CONV_C][ROWS_S][COLS_S];              // 8*14*66*4 = 29568 B
    __shared__ __align__(16) float2 sWd[CONV_C * 9][CONV_M];   // 72*8*8    =  4608 B

    const int tx  = threadIdx.x;            // 0..31  (column pair)
    const int ty  = threadIdx.y;            // 0..7
    const int tid = ty * 32 + tx;

    const int mh    = (ty & 1) * MH;        // m-half: 0 or 4
    const int rbase = (ty >> 1) * JPT;      // row group: 0,3,6,9

    const int col0 = blockIdx.x * TILE_W;   // 0,64,128,192
    const int row0 = blockIdx.y * TILE_H;   // 0..252
    const int n    = blockIdx.z;

    const float* inN = in + (size_t)n * CONV_C * CONV_H * CONV_W;

    // ---- stage all 8 channels of the halo tile via cp.async (float2).
    // 8*14*33 = 3696 float2 / 256 threads -> 15 iters (last partial).
    // OOB rows clamped to 255, OOB col-pairs clamped to start 254; clamped
    // values only feed outputs the store clips.
    {
        float* sInFlat = &sIn[0][0][0];
#pragma unroll
        for (int k = 0; k < 15; k++) {
            int i = tid + k * 256;
            if (i < CONV_C * ROWS_S * 33) {
                int cp  = i % 33;
                int t   = i / 33;
                int row = t % ROWS_S;
                int cl  = t / ROWS_S;
                int gr = row0 + row;     if (gr > CONV_H - 1) gr = CONV_H - 1;
                int gc = col0 + 2 * cp;  if (gc > CONV_W - 2) gc = CONV_W - 2;
                const float* src = &inN[((size_t)cl * CONV_H + gr) * CONV_W + gc];
                unsigned smem_addr =
                    (unsigned)__cvta_generic_to_shared(&sInFlat[2 * i]);
                asm volatile("cp.async.ca.shared.global [%0], [%1], 8;"
                             :: "r"(smem_addr), "l"(src));
            }
        }
        asm volatile("cp.async.commit_group;");
    }

    // ---- filter, duplicated pairs: sWd[rem][m] = {w, w};  rem=(c*3+r)*3+s
    for (int i = tid; i < CONV_M * CONV_C * 9; i += 256) {
        int m   = i / 72;
        int rem = i % 72;
        float w = filt[m * 72 + rem];
        sWd[rem][m] = make_float2(w, w);
    }

    ull acc[JPT][MH];
#pragma unroll
    for (int j = 0; j < JPT; j++)
#pragma unroll
        for (int m = 0; m < MH; m++) acc[j][m] = 0ull;

    const int q2 = 2 * tx;

    asm volatile("cp.async.wait_group 0;");
    __syncthreads();

    // ---- compute: fully unrolled; all LDS offsets are [Rbase + immediate].
#pragma unroll
    for (int cl = 0; cl < CONV_C; cl++) {
#pragma unroll
        for (int r = 0; r < 3; r++) {
            // 3 input rows for this r as packed column pairs:
            // xa={x0,x1} xb={x2,x3} direct LDS.64; xm={x1,x2} one pack.
            ull xa[JPT], xb[JPT], xm[JPT];
#pragma unroll
            for (int j = 0; j < JPT; j++) {
                const float* p = &sIn[cl][rbase + r + j][q2];
                xa[j] = *reinterpret_cast<const ull*>(p);
                xb[j] = *reinterpret_cast<const ull*>(p + 2);
                asm("{\n\t"
                    ".reg .f32 a,b,cc,d;\n\t"
                    "mov.b64 {a,b}, %1;\n\t"
                    "mov.b64 {cc,d}, %2;\n\t"
                    "mov.b64 %0, {b,cc};\n\t"
                    "}"
                    : "=l"(xm[j]) : "l"(xa[j]), "l"(xb[j]));
            }

#pragma unroll
            for (int s = 0; s < 3; s++) {
                // this thread's 4 duplicated weight pairs: 2x LDS.128 broadcast
                ull w2[MH];
                const ulonglong2* wrow = reinterpret_cast<const ulonglong2*>(
                    &sWd[(cl * 3 + r) * 3 + s][mh]);
#pragma unroll
                for (int h = 0; h < MH / 2; h++) {
                    ulonglong2 v = wrow[h];
                    w2[2 * h]     = v.x;
                    w2[2 * h + 1] = v.y;
                }

#pragma unroll
                for (int j = 0; j < JPT; j++) {
                    ull xv = (s == 0) ? xa[j] : (s == 1) ? xm[j] : xb[j];
#pragma unroll
                    for (int m = 0; m < MH; m++) {
                        asm("fma.rn.f32x2 %0, %1, %2, %0;"
                            : "+l"(acc[j][m])
                            : "l"(xv), "l"(w2[m]));
                    }
                }
            }
        }
    }

    // ---- store: out[n][mh+m][orow][ocol], column pair via STG.64
    const int ocol = col0 + q2;
    float* outN = out + (size_t)n * CONV_M * CONV_P * CONV_Q;
    if (ocol < CONV_Q) {
#pragma unroll
        for (int j = 0; j < JPT; j++) {
            int orow = row0 + rbase + j;
            if (orow < CONV_P) {
#pragma unroll
                for (int m = 0; m < MH; m++) {
                    *reinterpret_cast<ull*>(
                        &outN[((size_t)(mh + m) * CONV_P + orow) * CONV_Q + ocol]) = acc[j][m];
                }
            }
        }
    }
}

extern "C" void kernel_launch(void* const* d_in, const int* in_sizes, int n_in,
                              void* d_out, int out_size)
{
    const float* input  = (const float*)d_in[0];   // (64,8,256,256)
    const float* filter = (const float*)d_in[1];   // (8,8,3,3)
    float* output = (float*)d_out;                 // (64,8,254,254)

    dim3 block(32, 8, 1);
    dim3 grid((CONV_Q + TILE_W - 1) / TILE_W,      // 4
              (CONV_P + TILE_H - 1) / TILE_H,      // 22
              CONV_N);                             // 64
    Im2Col_Conv2d_6854767804820_kernel<<<grid, block>>>(input, filter, output);
}

// round 8
// speedup vs baseline: 1.6796x; 1.6796x over previous
#include <cuda_runtime.h>
#include <cstdint>

// Conv2d direct: input (64,8,256,256) f32 NCHW, filter (8,8,3,3) OIHW,
// VALID, stride 1 -> out (64,8,254,254) f32.
//
// R7: R5 config (the 146us winner: 64x16 tile, JPT=4, MH=4, 3 CTAs/SM,
// fully-unrolled channels, cp.async staging) + cross-r input row caching:
// the 6 distinct input rows per channel are loaded ONCE (12 LDS.64) instead
// of per-r (24 LDS.64). Cuts L1TEX wavefronts/channel 66->42, which R6
// showed is the co-binding resource.

#define CONV_N 64
#define CONV_C 8
#define CONV_H 256
#define CONV_W 256
#define CONV_M 8
#define CONV_P 254
#define CONV_Q 254

#define TILE_W 64      // 32 threads x 2 cols
#define TILE_H 16      // 4 row-groups x 4 rows
#define JPT 4          // rows per thread
#define MH  4          // m channels per thread (half of 8)

#define ROWS_S (TILE_H + 2)   // 18
#define COLS_S 66

typedef unsigned long long ull;

__global__ __launch_bounds__(256, 3)
void Im2Col_Conv2d_6854767804820_kernel(const float* __restrict__ in,
                                        const float* __restrict__ filt,
                                        float* __restrict__ out)
{
    __shared__ float sIn[CONV_C][ROWS_S][COLS_S];              // 8*18*66*4 = 38016 B
    __shared__ __align__(16) float2 sWd[CONV_C * 9][CONV_M];   // 72*8*8    =  4608 B

    const int tx  = threadIdx.x;            // 0..31  (column pair)
    const int ty  = threadIdx.y;            // 0..7
    const int tid = ty * 32 + tx;

    const int mh    = (ty & 1) * MH;        // m-half: 0 or 4
    const int rbase = (ty >> 1) * JPT;      // row group: 0,4,8,12

    const int col0 = blockIdx.x * TILE_W;   // 0,64,128,192
    const int row0 = blockIdx.y * TILE_H;   // 0..240
    const int n    = blockIdx.z;

    const float* inN = in + (size_t)n * CONV_C * CONV_H * CONV_W;

    // ---- stage all 8 channels of the halo tile via cp.async (float2).
    // 8*18*33 = 4752 float2 / 256 threads -> 19 iters (last partial).
    // OOB rows clamped to 255, OOB col-pairs clamped to start 254; clamped
    // values only feed outputs the store clips.
    {
        float* sInFlat = &sIn[0][0][0];
#pragma unroll
        for (int k = 0; k < 19; k++) {
            int i = tid + k * 256;
            if (i < CONV_C * ROWS_S * 33) {
                int cp  = i % 33;
                int t   = i / 33;
                int row = t % ROWS_S;
                int cl  = t / ROWS_S;
                int gr = row0 + row;     if (gr > CONV_H - 1) gr = CONV_H - 1;
                int gc = col0 + 2 * cp;  if (gc > CONV_W - 2) gc = CONV_W - 2;
                const float* src = &inN[((size_t)cl * CONV_H + gr) * CONV_W + gc];
                unsigned smem_addr =
                    (unsigned)__cvta_generic_to_shared(&sInFlat[2 * i]);
                asm volatile("cp.async.ca.shared.global [%0], [%1], 8;"
                             :: "r"(smem_addr), "l"(src));
            }
        }
        asm volatile("cp.async.commit_group;");
    }

    // ---- filter, duplicated pairs: sWd[rem][m] = {w, w};  rem=(c*3+r)*3+s
    for (int i = tid; i < CONV_M * CONV_C * 9; i += 256) {
        int m   = i / 72;
        int rem = i % 72;
        float w = filt[m * 72 + rem];
        sWd[rem][m] = make_float2(w, w);
    }

    ull acc[JPT][MH];
#pragma unroll
    for (int j = 0; j < JPT; j++)
#pragma unroll
        for (int m = 0; m < MH; m++) acc[j][m] = 0ull;

    const int q2 = 2 * tx;

    asm volatile("cp.async.wait_group 0;");
    __syncthreads();

    // ---- compute: fully unrolled; all LDS offsets are [Rbase + immediate].
#pragma unroll
    for (int cl = 0; cl < CONV_C; cl++) {
        // Load the 6 distinct input rows this thread touches for this
        // channel ONCE: xa={x0,x1}, xb={x2,x3} as aligned LDS.64.
        ull xa[JPT + 2], xb[JPT + 2];
#pragma unroll
        for (int t = 0; t < JPT + 2; t++) {
            const float* p = &sIn[cl][rbase + t][q2];
            xa[t] = *reinterpret_cast<const ull*>(p);
            xb[t] = *reinterpret_cast<const ull*>(p + 2);
        }

#pragma unroll
        for (int r = 0; r < 3; r++) {
            // middle pairs xm={x1,x2} for the 4 rows of this r (transient)
            ull xm[JPT];
#pragma unroll
            for (int j = 0; j < JPT; j++) {
                asm("{\n\t"
                    ".reg .f32 a,b,cc,d;\n\t"
                    "mov.b64 {a,b}, %1;\n\t"
                    "mov.b64 {cc,d}, %2;\n\t"
                    "mov.b64 %0, {b,cc};\n\t"
                    "}"
                    : "=l"(xm[j]) : "l"(xa[r + j]), "l"(xb[r + j]));
            }

#pragma unroll
            for (int s = 0; s < 3; s++) {
                // this thread's 4 duplicated weight pairs: 2x LDS.128 broadcast
                ull w2[MH];
                const ulonglong2* wrow = reinterpret_cast<const ulonglong2*>(
                    &sWd[(cl * 3 + r) * 3 + s][mh]);
#pragma unroll
                for (int h = 0; h < MH / 2; h++) {
                    ulonglong2 v = wrow[h];
                    w2[2 * h]     = v.x;
                    w2[2 * h + 1] = v.y;
                }

#pragma unroll
                for (int j = 0; j < JPT; j++) {
                    ull xv = (s == 0) ? xa[r + j] : (s == 1) ? xm[j] : xb[r + j];
#pragma unroll
                    for (int m = 0; m < MH; m++) {
                        asm("fma.rn.f32x2 %0, %1, %2, %0;"
                            : "+l"(acc[j][m])
                            : "l"(xv), "l"(w2[m]));
                    }
                }
            }
        }
    }

    // ---- store: out[n][mh+m][orow][ocol], column pair via STG.64
    const int ocol = col0 + q2;
    float* outN = out + (size_t)n * CONV_M * CONV_P * CONV_Q;
    if (ocol < CONV_Q) {
#pragma unroll
        for (int j = 0; j < JPT; j++) {
            int orow = row0 + rbase + j;
            if (orow < CONV_P) {
#pragma unroll
                for (int m = 0; m < MH; m++) {
                    *reinterpret_cast<ull*>(
                        &outN[((size_t)(mh + m) * CONV_P + orow) * CONV_Q + ocol]) = acc[j][m];
                }
            }
        }
    }
}

extern "C" void kernel_launch(void* const* d_in, const int* in_sizes, int n_in,
                              void* d_out, int out_size)
{
    const float* input  = (const float*)d_in[0];   // (64,8,256,256)
    const float* filter = (const float*)d_in[1];   // (8,8,3,3)
    float* output = (float*)d_out;                 // (64,8,254,254)

    dim3 block(32, 8, 1);
    dim3 grid((CONV_Q + TILE_W - 1) / TILE_W,      // 4
              (CONV_P + TILE_H - 1) / TILE_H,      // 16
              CONV_N);                             // 64
    Im2Col_Conv2d_6854767804820_kernel<<<grid, block>>>(input, filter, output);
}

// round 10
// speedup vs baseline: 3.2391x; 1.9285x over previous
#include <cuda_runtime.h>
#include <cstdint>

// Conv2d via warp-level mma.sync tf32 implicit GEMM (sm_103 baseline PTX —
// tcgen05 is unavailable because the harness builds .target sm_103, not 103a).
//
// input (64,8,256,256) f32 NCHW, filter (8,8,3,3) OIHW, VALID -> (64,8,254,254).
//
// D[16 pix][8 m] += A[16 pix][8 c] x B[8 c][8 m] per tap (r,s): 9 x
// mma.sync.aligned.m16n8k8.row.col.f32.tf32.tf32.f32.
// Per warp: 16 q-columns x 16 p-rows x all 8 m. Weights in 18 registers.
// SMEM input tile [c][row][col] (col padded to 132 -> plane stride 2376 === 8
// mod 32 -> every A-fragment LDS.32 is bank-conflict-free).

#define NTHREADS 256
#define STRIP    16
#define COLS_P   132            // padded cols per row
#define PLANE    2376           // 18 * 132 floats per channel plane
#define SMEM_FLOATS (8 * PLANE) // 19008 floats = 76032 B

__device__ __forceinline__ uint32_t tf32_bits(float x) {
    uint32_t u;
    asm("cvt.rna.tf32.f32 %0, %1;" : "=r"(u) : "f"(x));
    return u;
}

__global__ __launch_bounds__(NTHREADS)
void Im2Col_Conv2d_6854767804820_kernel(const float* __restrict__ in,
                                        const float* __restrict__ filt,
                                        float* __restrict__ out)
{
    extern __shared__ float sm[];   // [c][row 0..17][col 0..131]

    const int tid  = threadIdx.x;
    const int w    = tid >> 5;          // warp 0..7
    const int lane = tid & 31;
    const int g    = lane >> 2;         // groupID: pixel ofs / m index
    const int t    = lane & 3;          // threadID_in_group: c / k index

    const int q0 = blockIdx.x * 128;    // 0 or 128
    const int p0 = blockIdx.y * STRIP;  // 0..240
    const int n  = blockIdx.z;
    const int np = min(STRIP, 254 - p0);

    const float* inN = in + (size_t)n * 524288;   // 8*256*256

    // ---- B fragments: b[r][s][0] = B[k=t][n=g] = filt[g][t][r][s]
    //                   b[r][s][1] = filt[g][t+4][r][s]
    uint32_t b[3][3][2];
#pragma unroll
    for (int r = 0; r < 3; r++)
#pragma unroll
        for (int s = 0; s < 3; s++) {
            b[r][s][0] = tf32_bits(__ldg(&filt[g * 72 + t * 9 + r * 3 + s]));
            b[r][s][1] = tf32_bits(__ldg(&filt[g * 72 + (t + 4) * 9 + r * 3 + s]));
        }

    // ---- stage input tile: 8 c-planes x 18 rows x 33 float4-groups = 4752 jobs.
    // Flat float4-slot j == (c*594 + row*33 + g4)  -> coalesced LDG.128/STS.128.
#pragma unroll
    for (int k = 0; k < 19; k++) {
        int j = tid + k * NTHREADS;
        if (j < 4752) {
            int c   = j / 594;
            int rem = j - c * 594;
            int row = rem / 33;
            int g4  = rem - row * 33;
            int gr  = p0 + row; if (gr > 255) gr = 255;
            int gcb = q0 + g4 * 4;
            const float* src = inN + c * 65536 + gr * 256 + gcb;
            float4 v;
            if (gcb + 3 <= 255) {
                v = *reinterpret_cast<const float4*>(src);
            } else {
                int c0 = min(gcb,     255), c1 = min(gcb + 1, 255);
                int c2 = min(gcb + 2, 255), c3 = min(gcb + 3, 255);
                const float* rowp = inN + c * 65536 + gr * 256;
                v = make_float4(rowp[c0], rowp[c1], rowp[c2], rowp[c3]);
            }
            uint4 u;
            u.x = tf32_bits(v.x); u.y = tf32_bits(v.y);
            u.z = tf32_bits(v.z); u.w = tf32_bits(v.w);
            reinterpret_cast<uint4*>(sm)[j] = u;
        }
    }
    __syncthreads();

    // ---- compute
    const int qw    = w * 16;                    // warp's q offset in tile
    const int laneA = t * PLANE + qw + g;        // A0 base (floats)
    const int qg    = q0 + qw + g;               // global q of pixels g / g+8
    const int m0    = 2 * t;                     // output channels of c0/c2
    const int m1    = 2 * t + 1;

    float* outN = out + (size_t)n * 516128;      // 8*254*254

    for (int i = 0; i < np; i++) {
        float d0 = 0.f, d1 = 0.f, d2 = 0.f, d3 = 0.f;
        const float* pb = sm + laneA + i * COLS_P;

#pragma unroll
        for (int r = 0; r < 3; r++) {
#pragma unroll
            for (int s = 0; s < 3; s++) {
                const float* pa = pb + r * COLS_P + s;
                uint32_t a0 = __float_as_uint(pa[0]);        // pix g,   k=t
                uint32_t a1 = __float_as_uint(pa[8]);        // pix g+8, k=t
                uint32_t a2 = __float_as_uint(pa[4 * PLANE]);     // pix g,   k=t+4
                uint32_t a3 = __float_as_uint(pa[4 * PLANE + 8]); // pix g+8, k=t+4
                asm volatile(
                    "mma.sync.aligned.m16n8k8.row.col.f32.tf32.tf32.f32 "
                    "{%0,%1,%2,%3}, {%4,%5,%6,%7}, {%8,%9}, {%0,%1,%2,%3};"
                    : "+f"(d0), "+f"(d1), "+f"(d2), "+f"(d3)
                    : "r"(a0), "r"(a1), "r"(a2), "r"(a3),
                      "r"(b[r][s][0]), "r"(b[r][s][1]));
            }
        }

        // D: c0=(pix g, m0)  c1=(pix g, m1)  c2=(pix g+8, m0)  c3=(pix g+8, m1)
        float* ob = outN + (size_t)(p0 + i) * 254 + qg;
        if (qg < 254) {
            ob[(size_t)m0 * 64516] = d0;
            ob[(size_t)m1 * 64516] = d1;
        }
        if (qg + 8 < 254) {
            ob[(size_t)m0 * 64516 + 8] = d2;
            ob[(size_t)m1 * 64516 + 8] = d3;
        }
    }
}

extern "C" void kernel_launch(void* const* d_in, const int* in_sizes, int n_in,
                              void* d_out, int out_size)
{
    const float* input  = (const float*)d_in[0];   // (64,8,256,256)
    const float* filter = (const float*)d_in[1];   // (8,8,3,3)
    float* output = (float*)d_out;                 // (64,8,254,254)

    static int attr_set = 0;
    if (!attr_set) {
        cudaFuncSetAttribute(Im2Col_Conv2d_6854767804820_kernel,
                             cudaFuncAttributeMaxDynamicSharedMemorySize,
                             SMEM_FLOATS * 4);
        attr_set = 1;
    }

    dim3 grid(2, 16, 64);   // q-half, p-strip, n
    Im2Col_Conv2d_6854767804820_kernel<<<grid, NTHREADS, SMEM_FLOATS * 4>>>(
        input, filter, output);
}

// round 12
// speedup vs baseline: 3.4374x; 1.0612x over previous
#include <cuda_runtime.h>
#include <cstdint>

// Conv2d via warp-level mma.sync tf32 implicit GEMM.
// input (64,8,256,256) f32 NCHW, filter (8,8,3,3) OIHW, VALID -> (64,8,254,254).
//
// R10: R9 + 3-row register window across the p-loop. Row i's taps r=0..2 read
// smem rows i..i+2; instead of 36 LDS.32 per row, keep the 12 floats per row
// in registers and load only the new row each iteration (192 vs 576 LDS.32
// per thread). p-loop fully unrolled (16) so the %3 window index is
// compile-time: zero rotation MOVs. L1TEX was the 67.7% binder in R9.

#define NTHREADS 256
#define STRIP    16
#define COLS_P   132            // padded cols per row
#define PLANE    2376           // 18 * 132 floats per channel plane (=== 8 mod 32)
#define SMEM_FLOATS (8 * PLANE) // 19008 floats = 76032 B

__device__ __forceinline__ uint32_t tf32_bits(float x) {
    uint32_t u;
    asm("cvt.rna.tf32.f32 %0, %1;" : "=r"(u) : "f"(x));
    return u;
}

__global__ __launch_bounds__(NTHREADS)
void Im2Col_Conv2d_6854767804820_kernel(const float* __restrict__ in,
                                        const float* __restrict__ filt,
                                        float* __restrict__ out)
{
    extern __shared__ float sm[];   // [c][row 0..17][col 0..131], tf32 bits

    const int tid  = threadIdx.x;
    const int w    = tid >> 5;          // warp 0..7
    const int lane = tid & 31;
    const int g    = lane >> 2;         // groupID: pixel ofs / m index
    const int t    = lane & 3;          // threadID_in_group: c / k index

    const int q0 = blockIdx.x * 128;    // 0 or 128
    const int p0 = blockIdx.y * STRIP;  // 0..240
    const int n  = blockIdx.z;

    const float* inN = in + (size_t)n * 524288;   // 8*256*256

    // ---- B fragments: b[r][s][0] = filt[g][t][r][s], b[r][s][1] = filt[g][t+4][r][s]
    uint32_t b[3][3][2];
#pragma unroll
    for (int r = 0; r < 3; r++)
#pragma unroll
        for (int s = 0; s < 3; s++) {
            b[r][s][0] = tf32_bits(__ldg(&filt[g * 72 + t * 9 + r * 3 + s]));
            b[r][s][1] = tf32_bits(__ldg(&filt[g * 72 + (t + 4) * 9 + r * 3 + s]));
        }

    // ---- stage input tile: 8 c-planes x 18 rows x 33 float4-groups = 4752 jobs.
#pragma unroll
    for (int k = 0; k < 19; k++) {
        int j = tid + k * NTHREADS;
        if (j < 4752) {
            int c   = j / 594;
            int rem = j - c * 594;
            int row = rem / 33;
            int g4  = rem - row * 33;
            int gr  = p0 + row; if (gr > 255) gr = 255;
            int gcb = q0 + g4 * 4;
            const float* src = inN + c * 65536 + gr * 256 + gcb;
            float4 v;
            if (gcb + 3 <= 255) {
                v = *reinterpret_cast<const float4*>(src);
            } else {
                int c0 = min(gcb,     255), c1 = min(gcb + 1, 255);
                int c2 = min(gcb + 2, 255), c3 = min(gcb + 3, 255);
                const float* rowp = inN + c * 65536 + gr * 256;
                v = make_float4(rowp[c0], rowp[c1], rowp[c2], rowp[c3]);
            }
            uint4 u;
            u.x = tf32_bits(v.x); u.y = tf32_bits(v.y);
            u.z = tf32_bits(v.z); u.w = tf32_bits(v.w);
            reinterpret_cast<uint4*>(sm)[j] = u;
        }
    }
    __syncthreads();

    // ---- compute
    const int qw = w * 16;                       // warp's q offset in tile
    const int qg = q0 + qw + g;                  // global q of pixels g / g+8
    const int m0 = 2 * t;
    const int m1 = 2 * t + 1;

    const float* base = sm + t * PLANE + qw + g;

    // register window: win[slot][k2*6 + pix*3 + s], slot = row % 3
    float win[3][12];

#define LOAD_ROW(slot, j)                                                     \
    {                                                                         \
        const float* p_ = base + (j) * COLS_P;                                \
        _Pragma("unroll")                                                     \
        for (int k2_ = 0; k2_ < 2; k2_++)                                     \
            _Pragma("unroll")                                                 \
            for (int px_ = 0; px_ < 2; px_++)                                 \
                _Pragma("unroll")                                             \
                for (int s_ = 0; s_ < 3; s_++)                                \
                    win[slot][k2_ * 6 + px_ * 3 + s_] =                       \
                        p_[k2_ * 4 * PLANE + px_ * 8 + s_];                   \
    }

    LOAD_ROW(0, 0)
    LOAD_ROW(1, 1)
    LOAD_ROW(2, 2)

    float* outN = out + (size_t)n * 516128;      // 8*254*254

#pragma unroll
    for (int i = 0; i < STRIP; i++) {
        float d0 = 0.f, d1 = 0.f, d2 = 0.f, d3 = 0.f;

#pragma unroll
        for (int r = 0; r < 3; r++) {
            const int slot = (i + r) % 3;        // compile-time (loop unrolled)
#pragma unroll
            for (int s = 0; s < 3; s++) {
                uint32_t a0 = __float_as_uint(win[slot][0 * 6 + 0 * 3 + s]); // pix g,   k=t
                uint32_t a1 = __float_as_uint(win[slot][0 * 6 + 1 * 3 + s]); // pix g+8, k=t
                uint32_t a2 = __float_as_uint(win[slot][1 * 6 + 0 * 3 + s]); // pix g,   k=t+4
                uint32_t a3 = __float_as_uint(win[slot][1 * 6 + 1 * 3 + s]); // pix g+8, k=t+4
                asm volatile(
                    "mma.sync.aligned.m16n8k8.row.col.f32.tf32.tf32.f32 "
                    "{%0,%1,%2,%3}, {%4,%5,%6,%7}, {%8,%9}, {%0,%1,%2,%3};"
                    : "+f"(d0), "+f"(d1), "+f"(d2), "+f"(d3)
                    : "r"(a0), "r"(a1), "r"(a2), "r"(a3),
                      "r"(b[r][s][0]), "r"(b[r][s][1]));
            }
        }

        // D: c0=(pix g, m0) c1=(pix g, m1) c2=(pix g+8, m0) c3=(pix g+8, m1)
        if (p0 + i < 254) {
            float* ob = outN + (size_t)(p0 + i) * 254 + qg;
            if (qg < 254) {
                ob[(size_t)m0 * 64516] = d0;
                ob[(size_t)m1 * 64516] = d1;
            }
            if (qg + 8 < 254) {
                ob[(size_t)m0 * 64516 + 8] = d2;
                ob[(size_t)m1 * 64516 + 8] = d3;
            }
        }

        if (i < STRIP - 1) LOAD_ROW(i % 3, i + 3)
    }
#undef LOAD_ROW
}

extern "C" void kernel_launch(void* const* d_in, const int* in_sizes, int n_in,
                              void* d_out, int out_size)
{
    const float* input  = (const float*)d_in[0];   // (64,8,256,256)
    const float* filter = (const float*)d_in[1];   // (8,8,3,3)
    float* output = (float*)d_out;                 // (64,8,254,254)

    static int attr_set = 0;
    if (!attr_set) {
        cudaFuncSetAttribute(Im2Col_Conv2d_6854767804820_kernel,
                             cudaFuncAttributeMaxDynamicSharedMemorySize,
                             SMEM_FLOATS * 4);
        attr_set = 1;
    }

    dim3 grid(2, 16, 64);   // q-half, p-strip, n
    Im2Col_Conv2d_6854767804820_kernel<<<grid, NTHREADS, SMEM_FLOATS * 4>>>(
        input, filter, output);
}

// round 13
// speedup vs baseline: 4.0249x; 1.1709x over previous
#include <cuda_runtime.h>
#include <cstdint>

// Conv2d via warp-level mma.sync tf32 implicit GEMM.
// input (64,8,256,256) f32 NCHW, filter (8,8,3,3) OIHW, VALID -> (64,8,254,254).
//
// R11: R10 + STRIP 16->8 so smem/CTA drops 76KB -> 42.2KB => 4 CTAs/SM
// (occ 35% -> 50%). Nothing was saturated (L1 58.6, issue 33): the kernel is
// latency-bound, so resident warps are the lever. PLANE=1320 === 8 mod 32
// keeps the A-fragment LDS bank-conflict-free property.

#define NTHREADS 256
#define STRIP    8
#define ROWS_S   (STRIP + 2)        // 10
#define COLS_P   132                // padded cols per row
#define PLANE    (ROWS_S * COLS_P)  // 1320 floats (=== 8 mod 32)
#define SMEM_FLOATS (8 * PLANE)     // 10560 floats = 42240 B

__device__ __forceinline__ uint32_t tf32_bits(float x) {
    uint32_t u;
    asm("cvt.rna.tf32.f32 %0, %1;" : "=r"(u) : "f"(x));
    return u;
}

__global__ __launch_bounds__(NTHREADS, 4)
void Im2Col_Conv2d_6854767804820_kernel(const float* __restrict__ in,
                                        const float* __restrict__ filt,
                                        float* __restrict__ out)
{
    extern __shared__ float sm[];   // [c][row 0..9][col 0..131], tf32 bits

    const int tid  = threadIdx.x;
    const int w    = tid >> 5;          // warp 0..7
    const int lane = tid & 31;
    const int g    = lane >> 2;         // groupID: pixel ofs / m index
    const int t    = lane & 3;          // threadID_in_group: c / k index

    const int q0 = blockIdx.x * 128;    // 0 or 128
    const int p0 = blockIdx.y * STRIP;  // 0..248
    const int n  = blockIdx.z;

    const float* inN = in + (size_t)n * 524288;   // 8*256*256

    // ---- B fragments: b[r][s][0] = filt[g][t][r][s], b[r][s][1] = filt[g][t+4][r][s]
    uint32_t b[3][3][2];
#pragma unroll
    for (int r = 0; r < 3; r++)
#pragma unroll
        for (int s = 0; s < 3; s++) {
            b[r][s][0] = tf32_bits(__ldg(&filt[g * 72 + t * 9 + r * 3 + s]));
            b[r][s][1] = tf32_bits(__ldg(&filt[g * 72 + (t + 4) * 9 + r * 3 + s]));
        }

    // ---- stage input tile: 8 c-planes x 10 rows x 33 float4-groups = 2640 jobs.
#pragma unroll
    for (int k = 0; k < 11; k++) {
        int j = tid + k * NTHREADS;
        if (j < 2640) {
            int c   = j / 330;
            int rem = j - c * 330;
            int row = rem / 33;
            int g4  = rem - row * 33;
            int gr  = p0 + row; if (gr > 255) gr = 255;
            int gcb = q0 + g4 * 4;
            const float* src = inN + c * 65536 + gr * 256 + gcb;
            float4 v;
            if (gcb + 3 <= 255) {
                v = *reinterpret_cast<const float4*>(src);
            } else {
                // OOB columns feed only clipped outputs; any value works.
                int c0 = min(gcb,     255), c1 = min(gcb + 1, 255);
                int c2 = min(gcb + 2, 255), c3 = min(gcb + 3, 255);
                const float* rowp = inN + c * 65536 + gr * 256;
                v = make_float4(rowp[c0], rowp[c1], rowp[c2], rowp[c3]);
            }
            uint4 u;
            u.x = tf32_bits(v.x); u.y = tf32_bits(v.y);
            u.z = tf32_bits(v.z); u.w = tf32_bits(v.w);
            reinterpret_cast<uint4*>(sm)[j] = u;
        }
    }
    __syncthreads();

    // ---- compute
    const int qw = w * 16;                       // warp's q offset in tile
    const int qg = q0 + qw + g;                  // global q of pixels g / g+8
    const int m0 = 2 * t;
    const int m1 = 2 * t + 1;

    const float* base = sm + t * PLANE + qw + g;

    // register window: win[slot][k2*6 + pix*3 + s], slot = row % 3
    float win[3][12];

#define LOAD_ROW(slot, j)                                                     \
    {                                                                         \
        const float* p_ = base + (j) * COLS_P;                                \
        _Pragma("unroll")                                                     \
        for (int k2_ = 0; k2_ < 2; k2_++)                                     \
            _Pragma("unroll")                                                 \
            for (int px_ = 0; px_ < 2; px_++)                                 \
                _Pragma("unroll")                                             \
                for (int s_ = 0; s_ < 3; s_++)                                \
                    win[slot][k2_ * 6 + px_ * 3 + s_] =                       \
                        p_[k2_ * 4 * PLANE + px_ * 8 + s_];                   \
    }

    LOAD_ROW(0, 0)
    LOAD_ROW(1, 1)
    LOAD_ROW(2, 2)

    float* outN = out + (size_t)n * 516128;      // 8*254*254

#pragma unroll
    for (int i = 0; i < STRIP; i++) {
        float d0 = 0.f, d1 = 0.f, d2 = 0.f, d3 = 0.f;

#pragma unroll
        for (int r = 0; r < 3; r++) {
            const int slot = (i + r) % 3;        // compile-time (loop unrolled)
#pragma unroll
            for (int s = 0; s < 3; s++) {
                uint32_t a0 = __float_as_uint(win[slot][0 * 6 + 0 * 3 + s]); // pix g,   k=t
                uint32_t a1 = __float_as_uint(win[slot][0 * 6 + 1 * 3 + s]); // pix g+8, k=t
                uint32_t a2 = __float_as_uint(win[slot][1 * 6 + 0 * 3 + s]); // pix g,   k=t+4
                uint32_t a3 = __float_as_uint(win[slot][1 * 6 + 1 * 3 + s]); // pix g+8, k=t+4
                asm volatile(
                    "mma.sync.aligned.m16n8k8.row.col.f32.tf32.tf32.f32 "
                    "{%0,%1,%2,%3}, {%4,%5,%6,%7}, {%8,%9}, {%0,%1,%2,%3};"
                    : "+f"(d0), "+f"(d1), "+f"(d2), "+f"(d3)
                    : "r"(a0), "r"(a1), "r"(a2), "r"(a3),
                      "r"(b[r][s][0]), "r"(b[r][s][1]));
            }
        }

        // D: c0=(pix g, m0) c1=(pix g, m1) c2=(pix g+8, m0) c3=(pix g+8, m1)
        if (p0 + i < 254) {
            float* ob = outN + (size_t)(p0 + i) * 254 + qg;
            if (qg < 254) {
                ob[(size_t)m0 * 64516] = d0;
                ob[(size_t)m1 * 64516] = d1;
            }
            if (qg + 8 < 254) {
                ob[(size_t)m0 * 64516 + 8] = d2;
                ob[(size_t)m1 * 64516 + 8] = d3;
            }
        }

        if (i < STRIP - 1) LOAD_ROW(i % 3, i + 3)
    }
#undef LOAD_ROW
}

extern "C" void kernel_launch(void* const* d_in, const int* in_sizes, int n_in,
                              void* d_out, int out_size)
{
    const float* input  = (const float*)d_in[0];   // (64,8,256,256)
    const float* filter = (const float*)d_in[1];   // (8,8,3,3)
    float* output = (float*)d_out;                 // (64,8,254,254)

    static int attr_set = 0;
    if (!attr_set) {
        cudaFuncSetAttribute(Im2Col_Conv2d_6854767804820_kernel,
                             cudaFuncAttributeMaxDynamicSharedMemorySize,
                             SMEM_FLOATS * 4);
        attr_set = 1;
    }

    dim3 grid(2, 32, 64);   // q-half, p-strip (ceil(254/8)), n
    Im2Col_Conv2d_6854767804820_kernel<<<grid, NTHREADS, SMEM_FLOATS * 4>>>(
        input, filter, output);
}